// round 5
// baseline (speedup 1.0000x reference)
#include <cuda_runtime.h>
#include <cuda_bf16.h>
#include <cstdint>

#define DIM   128
#define HEADS 8
#define MAXD  12
#define PADV  3
#define NTOK  256
#define MSZ   (DIM*DIM)      // 16384
#define NMAT  16             // sos (prims[-1]) unused by reference output

// ---------------- device scratch ----------------
__device__ __align__(16) float g_X [NMAT*MSZ];
__device__ __align__(16) float g_X2[NMAT*MSZ];
__device__ __align__(16) float g_T0[NMAT*MSZ];
__device__ __align__(16) float g_T1[NMAT*MSZ];
__device__ __align__(16) float g_P [NMAT*MSZ];
__device__ __align__(16) __nv_bfloat16 g_Phi [NMAT*MSZ];
__device__ __align__(16) __nv_bfloat16 g_Plo [NMAT*MSZ];
__device__ __align__(16) __nv_bfloat16 g_PThi[NMAT*MSZ];
__device__ __align__(16) __nv_bfloat16 g_PTlo[NMAT*MSZ];
__device__ int g_pw[NTOK*MAXD];
__device__ int g_depth[NTOK];

// ---------------- helpers ----------------
__device__ __forceinline__ uint32_t smem_u32(const void* p) {
    uint32_t a;
    asm("{ .reg .u64 t; cvta.to.shared.u64 t, %1; cvt.u32.u64 %0, t; }" : "=r"(a) : "l"(p));
    return a;
}
#define STS128Q(a, r0, r1, r2, r3) \
    asm volatile("st.shared.v4.b32 [%0], {%1, %2, %3, %4};" \
                 :: "r"(a), "r"(r0), "r"(r1), "r"(r2), "r"(r3) : "memory")
#define LDSM4(r0, r1, r2, r3, addr) \
    asm volatile("ldmatrix.sync.aligned.m8n8.x4.shared.b16 {%0, %1, %2, %3}, [%4];" \
                 : "=r"(r0), "=r"(r1), "=r"(r2), "=r"(r3) : "r"(addr))
#define MMA16816(d, a, b) \
    asm volatile("mma.sync.aligned.m16n8k16.row.col.f32.bf16.bf16.f32 " \
                 "{%0, %1, %2, %3}, {%4, %5, %6, %7}, {%8, %9}, {%0, %1, %2, %3};" \
                 : "+f"((d)[0]), "+f"((d)[1]), "+f"((d)[2]), "+f"((d)[3]) \
                 : "r"((a)[0]), "r"((a)[1]), "r"((a)[2]), "r"((a)[3]), \
                   "r"((b)[0]), "r"((b)[1]))
// pack two f32 -> bf16x2 (lo in low half)
__device__ __forceinline__ uint32_t pack_bf2(float flo, float fhi) {
    uint32_t r;
    asm("cvt.rn.bf16x2.f32 %0, %1, %2;" : "=r"(r) : "f"(fhi), "f"(flo));
    return r;
}

// smem layout for k_maps (padded rows: 136 bf16 = 272 B; tile = 128*272 = 34816 B)
#define RSB     272
#define TILE_B  34816
#define OFF_MHI 0
#define OFF_MLO TILE_B
#define OFF_PT  (2*TILE_B)                 // + (sel*2 + half)*TILE_B
#define SMEM_MAPS (6*TILE_B)               // 208896 B

// load 128x128 bf16 row-major global -> padded smem rows
__device__ __forceinline__ void load_pad(uint32_t dst, const __nv_bfloat16* g,
                                         int t, int T) {
    const uint4* g4 = (const uint4*)g;
    for (int q = t; q < 2048; q += T) {
        uint4 v = g4[q];
        int r = q >> 4, c = (q & 15) << 3;      // c in elements
        STS128Q(dst + r * RSB + c * 2, v.x, v.y, v.z, v.w);
    }
}

// ---------------- K1: paths + steps ----------------
__global__ void k_paths(const int* __restrict__ positions,
                        float* __restrict__ steps_out, int write_steps)
{
    __shared__ int s_pw[NTOK][MAXD];
    __shared__ int s_dep[NTOK];
    int tid = threadIdx.x;
    {
        int d = positions[tid];
        int R[MAXD];
        int depth = 0;
#pragma unroll
        for (int t = 0; t < MAXD; t++) {
            if (d > 0) { R[t] = (d - 1) & 1; d = (d - 1) >> 1; depth++; }
            else       { R[t] = PADV; }
        }
#pragma unroll
        for (int t = 0; t < MAXD; t++) {
            int v = (t < depth) ? R[depth - 1 - t] : PADV;
            s_pw[tid][t] = v;
            g_pw[tid * MAXD + t] = v;
        }
        s_dep[tid] = depth;
        g_depth[tid] = depth;
    }
    __syncthreads();
    if (write_steps) {
        for (int idx = tid; idx < NTOK * NTOK; idx += blockDim.x) {
            int i = idx >> 8, j = idx & 255;
            int cpl = 0;
#pragma unroll
            for (int t = 0; t < MAXD; t++) {
                int a = s_pw[i][t];
                if (a != PADV && a == s_pw[j][t]) cpl++;
                else break;
            }
            steps_out[idx] = (float)(s_dep[i] + s_dep[j] - 2 * cpl);
        }
    }
}

// ---------------- K2a: X = (A - A^T) / 2^6 ----------------
__global__ void k_skew(const float* __restrict__ prim)
{
    int m = blockIdx.x;
    const float* A = prim + m * MSZ;
    float* X = g_X + m * MSZ;
    for (int e = threadIdx.x; e < MSZ; e += blockDim.x) {
        int i = e >> 7, j = e & 127;
        X[e] = (A[e] - A[j * DIM + i]) * (1.0f / 64.0f);
    }
}

// ---------------- K2b: expm GEMM, smem-staged, grid (16, 8) ----------------
// C = A@B [+ alpha*I + beta*X]; optionally T3 = c6 I + c7 X + c8 (A@B)
__global__ void k_egemm2(const float* __restrict__ Ab, const float* __restrict__ Bb,
                         float* __restrict__ Cb, const float* __restrict__ Xb,
                         float alpha, float beta, float* __restrict__ T3b,
                         int has_epi)
{
    extern __shared__ float sh[];
    float* As = sh;                 // 128 x 130 (padded)
    float* Bs = sh + 128 * 130;     // 128 x 16
    const float c6 = 1.0f / 720.0f, c7 = 1.0f / 5040.0f, c8 = 1.0f / 40320.0f;
    int m  = blockIdx.x;
    int cb = blockIdx.y;
    const float* A = Ab + m * MSZ;
    const float* B = Bb + m * MSZ + cb * 16;
    int tid = threadIdx.x;

    for (int e = tid; e < MSZ; e += 256) As[(e >> 7) * 130 + (e & 127)] = A[e];
    for (int e = tid; e < 2048; e += 256) Bs[e] = B[(e >> 4) * DIM + (e & 15)];
    __syncthreads();

    int tx = tid & 3, ty = tid >> 2;
    int i0 = ty * 2, k0 = tx * 4;
    float acc[2][4];
#pragma unroll
    for (int r = 0; r < 2; r++)
#pragma unroll
        for (int c = 0; c < 4; c++) acc[r][c] = 0.0f;

#pragma unroll 4
    for (int j = 0; j < DIM; j++) {
        float a0 = As[i0 * 130 + j];
        float a1 = As[(i0 + 1) * 130 + j];
        float4 b = *(const float4*)(Bs + j * 16 + k0);
        acc[0][0] = fmaf(a0, b.x, acc[0][0]);
        acc[0][1] = fmaf(a0, b.y, acc[0][1]);
        acc[0][2] = fmaf(a0, b.z, acc[0][2]);
        acc[0][3] = fmaf(a0, b.w, acc[0][3]);
        acc[1][0] = fmaf(a1, b.x, acc[1][0]);
        acc[1][1] = fmaf(a1, b.y, acc[1][1]);
        acc[1][2] = fmaf(a1, b.z, acc[1][2]);
        acc[1][3] = fmaf(a1, b.w, acc[1][3]);
    }

    int gk = cb * 16 + k0;
#pragma unroll
    for (int r = 0; r < 2; r++) {
        int gi = i0 + r;
        float raw[4] = {acc[r][0], acc[r][1], acc[r][2], acc[r][3]};
        float xv[4] = {0, 0, 0, 0};
        if (has_epi) {
            float4 x4 = *(const float4*)(Xb + m * MSZ + gi * DIM + gk);
            xv[0] = x4.x; xv[1] = x4.y; xv[2] = x4.z; xv[3] = x4.w;
        }
        float v[4];
#pragma unroll
        for (int c = 0; c < 4; c++) {
            float idv = (gi == gk + c) ? 1.0f : 0.0f;
            v[c] = raw[c] + (has_epi ? (alpha * idv + beta * xv[c]) : 0.0f);
        }
        *(float4*)(Cb + m * MSZ + gi * DIM + gk) = make_float4(v[0], v[1], v[2], v[3]);
        if (T3b) {
            float t[4];
#pragma unroll
            for (int c = 0; c < 4; c++) {
                float idv = (gi == gk + c) ? 1.0f : 0.0f;
                t[c] = c6 * idv + c7 * xv[c] + c8 * raw[c];
            }
            *(float4*)(T3b + m * MSZ + gi * DIM + gk) = make_float4(t[0], t[1], t[2], t[3]);
        }
    }
}

// ---------------- K2c: split P into bf16 hi/lo (+ transposed copies) ------
__global__ void k_split()
{
    int m = blockIdx.x;
    const float* P = g_P + m * MSZ;
    for (int e = threadIdx.x; e < MSZ; e += blockDim.x) {
        int i = e >> 7, j = e & 127;
        float x = P[e];
        __nv_bfloat16 hi = __float2bfloat16(x);
        __nv_bfloat16 lo = __float2bfloat16(x - __bfloat162float(hi));
        g_Phi [m * MSZ + e] = hi;
        g_Plo [m * MSZ + e] = lo;
        g_PThi[m * MSZ + j * DIM + i] = hi;   // PT[k][j] = P[j][k]
        g_PTlo[m * MSZ + j * DIM + i] = lo;
    }
}

// ---------------- K3: maps chain via mma.sync bf16 (3-term split) ---------
// D[i,k] = sum_j M[i,j] P[j,k]. A = M row-major (smem), B = PT rows (smem).
// Warp tile 64x32; 8 warps = 2x4 over the 128x128 output.
__global__ void __launch_bounds__(256) k_maps_mma(float* __restrict__ out)
{
    extern __shared__ char smem[];
    uint32_t sb = smem_u32(smem);
    int tid = threadIdx.x, wid = tid >> 5, lane = tid & 31;
    int n = blockIdx.x, h = blockIdx.y;
    int depth = g_depth[n];
    float* outm = out + (size_t)(n * HEADS + h) * MSZ;

    if (depth == 0) {
        for (int e = tid; e < MSZ; e += 256)
            outm[e] = ((e >> 7) == (e & 127)) ? 1.0f : 0.0f;
        return;
    }
    const int* pw = g_pw + n * MAXD;
    if (depth == 1) {
        const float4* src = (const float4*)(g_P + (size_t)(pw[0] * HEADS + h) * MSZ);
        float4* dst = (float4*)outm;
        for (int e = tid; e < MSZ / 4; e += 256) dst[e] = src[e];
        return;
    }

    // prologue: stage M = P(w0) hi/lo and PT(b) hi/lo for b = 0,1
    {
        size_t m0 = (size_t)(pw[0] * HEADS + h) * MSZ;
        size_t mb0 = (size_t)(0 * HEADS + h) * MSZ;
        size_t mb1 = (size_t)(1 * HEADS + h) * MSZ;
        load_pad(sb + OFF_MHI,              g_Phi  + m0,  tid, 256);
        load_pad(sb + OFF_MLO,              g_Plo  + m0,  tid, 256);
        load_pad(sb + OFF_PT + 0 * TILE_B,  g_PThi + mb0, tid, 256);
        load_pad(sb + OFF_PT + 1 * TILE_B,  g_PTlo + mb0, tid, 256);
        load_pad(sb + OFF_PT + 2 * TILE_B,  g_PThi + mb1, tid, 256);
        load_pad(sb + OFF_PT + 3 * TILE_B,  g_PTlo + mb1, tid, 256);
    }
    __syncthreads();

    // per-lane ldmatrix address components
    int m_base = (wid & 1) * 64;
    int n_base = (wid >> 1) * 32;
    int t  = lane >> 3;                    // tile group 0..3
    int r8 = lane & 7;
    int g  = lane >> 2;                    // mma output row-in-8
    int tig = lane & 3;
    // A frag mi: tiles (i0,j0),(i0+8,j0),(i0,j0+8),(i0+8,j0+8)
    uint32_t aOff[4];
#pragma unroll
    for (int mi = 0; mi < 4; mi++) {
        int row = m_base + mi * 16 + (t & 1) * 8 + r8;
        aOff[mi] = (uint32_t)(row * RSB + (t >> 1) * 16);
    }
    // B frag pair p covers ni=2p,2p+1: tiles (n0,j0),(n0,j0+8),(n0+8,j0),(n0+8,j0+8)
    uint32_t bOff[2];
#pragma unroll
    for (int p = 0; p < 2; p++) {
        int row = n_base + p * 16 + (t >> 1) * 8 + r8;
        bOff[p] = (uint32_t)(row * RSB + (t & 1) * 16);
    }

    for (int d = 1; d < depth; d++) {
        int sel = pw[d];
        uint32_t bBase = sb + OFF_PT + (uint32_t)(sel * 2) * TILE_B;  // hi; lo = +TILE_B

        float acc[4][4][4];
#pragma unroll
        for (int mi = 0; mi < 4; mi++)
#pragma unroll
            for (int ni = 0; ni < 4; ni++)
#pragma unroll
                for (int q = 0; q < 4; q++) acc[mi][ni][q] = 0.0f;

#pragma unroll
        for (int kk = 0; kk < 8; kk++) {
            uint32_t kb = (uint32_t)(kk * 32);
            uint32_t Ah[4][4], Al[4][4];
#pragma unroll
            for (int mi = 0; mi < 4; mi++) {
                uint32_t ah = sb + OFF_MHI + aOff[mi] + kb;
                LDSM4(Ah[mi][0], Ah[mi][1], Ah[mi][2], Ah[mi][3], ah);
                LDSM4(Al[mi][0], Al[mi][1], Al[mi][2], Al[mi][3], ah + TILE_B);
            }
            uint32_t Bh[4][2], Bl[4][2];
#pragma unroll
            for (int p = 0; p < 2; p++) {
                uint32_t bh = bBase + bOff[p] + kb;
                uint32_t r0, r1, r2, r3;
                LDSM4(r0, r1, r2, r3, bh);
                Bh[2*p][0] = r0; Bh[2*p][1] = r1; Bh[2*p+1][0] = r2; Bh[2*p+1][1] = r3;
                LDSM4(r0, r1, r2, r3, bh + TILE_B);
                Bl[2*p][0] = r0; Bl[2*p][1] = r1; Bl[2*p+1][0] = r2; Bl[2*p+1][1] = r3;
            }
#pragma unroll
            for (int mi = 0; mi < 4; mi++)
#pragma unroll
                for (int ni = 0; ni < 4; ni++) {
                    MMA16816(acc[mi][ni], Ah[mi], Bh[ni]);
                    MMA16816(acc[mi][ni], Ah[mi], Bl[ni]);
                    MMA16816(acc[mi][ni], Al[mi], Bh[ni]);
                }
        }
        __syncthreads();                   // all reads of M done

        if (d == depth - 1) {
            // final: accumulators -> global f32
#pragma unroll
            for (int mi = 0; mi < 4; mi++) {
                int row0 = m_base + mi * 16 + g;
#pragma unroll
                for (int ni = 0; ni < 4; ni++) {
                    int col = n_base + ni * 8 + tig * 2;
                    *(float2*)(outm + (size_t)row0 * DIM + col) =
                        make_float2(acc[mi][ni][0], acc[mi][ni][1]);
                    *(float2*)(outm + (size_t)(row0 + 8) * DIM + col) =
                        make_float2(acc[mi][ni][2], acc[mi][ni][3]);
                }
            }
        } else {
            // split accumulators -> M hi/lo in smem
#pragma unroll
            for (int mi = 0; mi < 4; mi++) {
                int row0 = m_base + mi * 16 + g;
#pragma unroll
                for (int ni = 0; ni < 4; ni++) {
                    int colb = (n_base + ni * 8 + tig * 2) * 2;
                    float c0 = acc[mi][ni][0], c1 = acc[mi][ni][1];
                    float c2 = acc[mi][ni][2], c3 = acc[mi][ni][3];
                    __nv_bfloat16 h0 = __float2bfloat16(c0);
                    __nv_bfloat16 h1 = __float2bfloat16(c1);
                    __nv_bfloat16 h2 = __float2bfloat16(c2);
                    __nv_bfloat16 h3 = __float2bfloat16(c3);
                    uint32_t hp01 = pack_bf2(c0, c1);   // rounds again; use packed hi
                    uint32_t hp23 = pack_bf2(c2, c3);
                    float l0 = c0 - __bfloat162float(h0);
                    float l1 = c1 - __bfloat162float(h1);
                    float l2 = c2 - __bfloat162float(h2);
                    float l3 = c3 - __bfloat162float(h3);
                    uint32_t lp01 = pack_bf2(l0, l1);
                    uint32_t lp23 = pack_bf2(l2, l3);
                    uint32_t a0 = sb + OFF_MHI + row0 * RSB + colb;
                    uint32_t a1 = sb + OFF_MHI + (row0 + 8) * RSB + colb;
                    asm volatile("st.shared.b32 [%0], %1;" :: "r"(a0), "r"(hp01) : "memory");
                    asm volatile("st.shared.b32 [%0], %1;" :: "r"(a1), "r"(hp23) : "memory");
                    asm volatile("st.shared.b32 [%0], %1;" :: "r"(a0 + TILE_B), "r"(lp01) : "memory");
                    asm volatile("st.shared.b32 [%0], %1;" :: "r"(a1 + TILE_B), "r"(lp23) : "memory");
                }
            }
            __syncthreads();
        }
    }
}

// ---------------- host launcher ----------------
extern "C" void kernel_launch(void* const* d_in, const int* in_sizes, int n_in,
                              void* d_out, int out_size)
{
    const float* prim      = (const float*)d_in[0];
    const int*   positions = (const int*)d_in[1];
    float*       out       = (float*)d_out;
    (void)in_sizes; (void)n_in;

    const int EG_SMEM = (128 * 130 + 128 * 16) * 4;
    cudaFuncSetAttribute(k_maps_mma, cudaFuncAttributeMaxDynamicSharedMemorySize, SMEM_MAPS);
    cudaFuncSetAttribute(k_egemm2, cudaFuncAttributeMaxDynamicSharedMemorySize, EG_SMEM);

    float *pX, *pX2, *pT0, *pT1, *pP;
    cudaGetSymbolAddress((void**)&pX,  g_X);
    cudaGetSymbolAddress((void**)&pX2, g_X2);
    cudaGetSymbolAddress((void**)&pT0, g_T0);
    cudaGetSymbolAddress((void**)&pT1, g_T1);
    cudaGetSymbolAddress((void**)&pP,  g_P);

    const int MAPS_ELEMS  = NTOK * HEADS * MSZ;
    const int STEPS_ELEMS = NTOK * NTOK;
    int write_steps = (out_size >= MAPS_ELEMS + STEPS_ELEMS) ? 1 : 0;
    float* steps_out = out + MAPS_ELEMS;

    k_paths<<<1, 256>>>(positions, steps_out, write_steps);

    // expm: X = skew/2^6; order-8 Taylor (Paterson-Stockmeyer); 6 squarings
    k_skew<<<NMAT, 256>>>(prim);
    const float c2 = 1.0f/2.0f, c3 = 1.0f/6.0f, c4 = 1.0f/24.0f, c5 = 1.0f/120.0f;
    dim3 gg(NMAT, 8);
    k_egemm2<<<gg, 256, EG_SMEM>>>(pX,  pX,  pX2, pX, 0.0f, 0.0f, pT0, 1);
    k_egemm2<<<gg, 256, EG_SMEM>>>(pX2, pT0, pT1, pX, c4, c5, nullptr, 1);
    k_egemm2<<<gg, 256, EG_SMEM>>>(pX2, pT1, pT0, pX, c2, c3, nullptr, 1);
    k_egemm2<<<gg, 256, EG_SMEM>>>(pX2, pT0, pT1, pX, 1.0f, 1.0f, nullptr, 1);
    k_egemm2<<<gg, 256, EG_SMEM>>>(pT1, pT1, pT0, nullptr, 0, 0, nullptr, 0);
    k_egemm2<<<gg, 256, EG_SMEM>>>(pT0, pT0, pT1, nullptr, 0, 0, nullptr, 0);
    k_egemm2<<<gg, 256, EG_SMEM>>>(pT1, pT1, pT0, nullptr, 0, 0, nullptr, 0);
    k_egemm2<<<gg, 256, EG_SMEM>>>(pT0, pT0, pT1, nullptr, 0, 0, nullptr, 0);
    k_egemm2<<<gg, 256, EG_SMEM>>>(pT1, pT1, pT0, nullptr, 0, 0, nullptr, 0);
    k_egemm2<<<gg, 256, EG_SMEM>>>(pT0, pT0, pP,  nullptr, 0, 0, nullptr, 0);

    // split P -> bf16 hi/lo (+transposed)
    k_split<<<NMAT, 256>>>();

    dim3 gm(NTOK, HEADS);
    k_maps_mma<<<gm, 256, SMEM_MAPS>>>(out);
}

// round 6
// speedup vs baseline: 1.0004x; 1.0004x over previous
#include <cuda_runtime.h>
#include <cuda_bf16.h>
#include <cstdint>

#define DIM   128
#define HEADS 8
#define MAXD  12
#define PADV  3
#define NTOK  256
#define MSZ   (DIM*DIM)      // 16384
#define NMAT  16             // sos (prims[-1]) unused by reference output

// ---------------- device scratch ----------------
__device__ __align__(16) float g_X [NMAT*MSZ];
__device__ __align__(16) float g_X2[NMAT*MSZ];
__device__ __align__(16) float g_T0[NMAT*MSZ];
__device__ __align__(16) float g_T1[NMAT*MSZ];
__device__ __align__(16) float g_P [NMAT*MSZ];
__device__ __align__(16) __nv_bfloat16 g_Phi [NMAT*MSZ];
__device__ __align__(16) __nv_bfloat16 g_Plo [NMAT*MSZ];
__device__ __align__(16) __nv_bfloat16 g_PThi[NMAT*MSZ];
__device__ __align__(16) __nv_bfloat16 g_PTlo[NMAT*MSZ];
__device__ int g_pw[NTOK*MAXD];
__device__ int g_depth[NTOK];

// ---------------- helpers ----------------
__device__ __forceinline__ uint32_t smem_u32(const void* p) {
    uint32_t a;
    asm("{ .reg .u64 t; cvta.to.shared.u64 t, %1; cvt.u32.u64 %0, t; }" : "=r"(a) : "l"(p));
    return a;
}
#define STS128Q(a, r0, r1, r2, r3) \
    asm volatile("st.shared.v4.b32 [%0], {%1, %2, %3, %4};" \
                 :: "r"(a), "r"(r0), "r"(r1), "r"(r2), "r"(r3) : "memory")
#define LDSM4(r0, r1, r2, r3, addr) \
    asm volatile("ldmatrix.sync.aligned.m8n8.x4.shared.b16 {%0, %1, %2, %3}, [%4];" \
                 : "=r"(r0), "=r"(r1), "=r"(r2), "=r"(r3) : "r"(addr))
#define MMA16816(d, a, b) \
    asm volatile("mma.sync.aligned.m16n8k16.row.col.f32.bf16.bf16.f32 " \
                 "{%0, %1, %2, %3}, {%4, %5, %6, %7}, {%8, %9}, {%0, %1, %2, %3};" \
                 : "+f"((d)[0]), "+f"((d)[1]), "+f"((d)[2]), "+f"((d)[3]) \
                 : "r"((a)[0]), "r"((a)[1]), "r"((a)[2]), "r"((a)[3]), \
                   "r"((b)[0]), "r"((b)[1]))
// pack two f32 -> bf16x2 (lo in low half)
__device__ __forceinline__ uint32_t pack_bf2(float flo, float fhi) {
    uint32_t r;
    asm("cvt.rn.bf16x2.f32 %0, %1, %2;" : "=r"(r) : "f"(fhi), "f"(flo));
    return r;
}

// smem layout for k_maps (padded rows: 136 bf16 = 272 B; tile = 128*272 = 34816 B)
#define RSB     272
#define TILE_B  34816
#define OFF_MHI 0
#define OFF_MLO TILE_B
#define OFF_PT  (2*TILE_B)                 // + (sel*2 + half)*TILE_B
#define SMEM_MAPS (6*TILE_B)               // 208896 B

// load 128x128 bf16 row-major global -> padded smem rows
__device__ __forceinline__ void load_pad(uint32_t dst, const __nv_bfloat16* g,
                                         int t, int T) {
    const uint4* g4 = (const uint4*)g;
    for (int q = t; q < 2048; q += T) {
        uint4 v = g4[q];
        int r = q >> 4, c = (q & 15) << 3;      // c in elements
        STS128Q(dst + r * RSB + c * 2, v.x, v.y, v.z, v.w);
    }
}

// ---------------- K1: paths + steps ----------------
__global__ void k_paths(const int* __restrict__ positions,
                        float* __restrict__ steps_out, int write_steps)
{
    __shared__ int s_pw[NTOK][MAXD];
    __shared__ int s_dep[NTOK];
    int tid = threadIdx.x;
    {
        int d = positions[tid];
        int R[MAXD];
        int depth = 0;
#pragma unroll
        for (int t = 0; t < MAXD; t++) {
            if (d > 0) { R[t] = (d - 1) & 1; d = (d - 1) >> 1; depth++; }
            else       { R[t] = PADV; }
        }
#pragma unroll
        for (int t = 0; t < MAXD; t++) {
            int v = (t < depth) ? R[depth - 1 - t] : PADV;
            s_pw[tid][t] = v;
            g_pw[tid * MAXD + t] = v;
        }
        s_dep[tid] = depth;
        g_depth[tid] = depth;
    }
    __syncthreads();
    if (write_steps) {
        for (int idx = tid; idx < NTOK * NTOK; idx += blockDim.x) {
            int i = idx >> 8, j = idx & 255;
            int cpl = 0;
#pragma unroll
            for (int t = 0; t < MAXD; t++) {
                int a = s_pw[i][t];
                if (a != PADV && a == s_pw[j][t]) cpl++;
                else break;
            }
            steps_out[idx] = (float)(s_dep[i] + s_dep[j] - 2 * cpl);
        }
    }
}

// ---------------- K2a: X = (A - A^T) / 2^6 ----------------
__global__ void k_skew(const float* __restrict__ prim)
{
    int m = blockIdx.x;
    const float* A = prim + m * MSZ;
    float* X = g_X + m * MSZ;
    for (int e = threadIdx.x; e < MSZ; e += blockDim.x) {
        int i = e >> 7, j = e & 127;
        X[e] = (A[e] - A[j * DIM + i]) * (1.0f / 64.0f);
    }
}

// ---------------- K2b: expm GEMM, smem-staged, grid (16, 8) ----------------
// C = A@B [+ alpha*I + beta*X]; optionally T3 = c6 I + c7 X + c8 (A@B)
__global__ void k_egemm2(const float* __restrict__ Ab, const float* __restrict__ Bb,
                         float* __restrict__ Cb, const float* __restrict__ Xb,
                         float alpha, float beta, float* __restrict__ T3b,
                         int has_epi)
{
    extern __shared__ float sh[];
    float* As = sh;                 // 128 x 130 (padded)
    float* Bs = sh + 128 * 130;     // 128 x 16
    const float c6 = 1.0f / 720.0f, c7 = 1.0f / 5040.0f, c8 = 1.0f / 40320.0f;
    int m  = blockIdx.x;
    int cb = blockIdx.y;
    const float* A = Ab + m * MSZ;
    const float* B = Bb + m * MSZ + cb * 16;
    int tid = threadIdx.x;

    for (int e = tid; e < MSZ; e += 256) As[(e >> 7) * 130 + (e & 127)] = A[e];
    for (int e = tid; e < 2048; e += 256) Bs[e] = B[(e >> 4) * DIM + (e & 15)];
    __syncthreads();

    int tx = tid & 3, ty = tid >> 2;
    int i0 = ty * 2, k0 = tx * 4;
    float acc[2][4];
#pragma unroll
    for (int r = 0; r < 2; r++)
#pragma unroll
        for (int c = 0; c < 4; c++) acc[r][c] = 0.0f;

#pragma unroll 4
    for (int j = 0; j < DIM; j++) {
        float a0 = As[i0 * 130 + j];
        float a1 = As[(i0 + 1) * 130 + j];
        float4 b = *(const float4*)(Bs + j * 16 + k0);
        acc[0][0] = fmaf(a0, b.x, acc[0][0]);
        acc[0][1] = fmaf(a0, b.y, acc[0][1]);
        acc[0][2] = fmaf(a0, b.z, acc[0][2]);
        acc[0][3] = fmaf(a0, b.w, acc[0][3]);
        acc[1][0] = fmaf(a1, b.x, acc[1][0]);
        acc[1][1] = fmaf(a1, b.y, acc[1][1]);
        acc[1][2] = fmaf(a1, b.z, acc[1][2]);
        acc[1][3] = fmaf(a1, b.w, acc[1][3]);
    }

    int gk = cb * 16 + k0;
#pragma unroll
    for (int r = 0; r < 2; r++) {
        int gi = i0 + r;
        float raw[4] = {acc[r][0], acc[r][1], acc[r][2], acc[r][3]};
        float xv[4] = {0, 0, 0, 0};
        if (has_epi) {
            float4 x4 = *(const float4*)(Xb + m * MSZ + gi * DIM + gk);
            xv[0] = x4.x; xv[1] = x4.y; xv[2] = x4.z; xv[3] = x4.w;
        }
        float v[4];
#pragma unroll
        for (int c = 0; c < 4; c++) {
            float idv = (gi == gk + c) ? 1.0f : 0.0f;
            v[c] = raw[c] + (has_epi ? (alpha * idv + beta * xv[c]) : 0.0f);
        }
        *(float4*)(Cb + m * MSZ + gi * DIM + gk) = make_float4(v[0], v[1], v[2], v[3]);
        if (T3b) {
            float t[4];
#pragma unroll
            for (int c = 0; c < 4; c++) {
                float idv = (gi == gk + c) ? 1.0f : 0.0f;
                t[c] = c6 * idv + c7 * xv[c] + c8 * raw[c];
            }
            *(float4*)(T3b + m * MSZ + gi * DIM + gk) = make_float4(t[0], t[1], t[2], t[3]);
        }
    }
}

// ---------------- K2c: split P into bf16 hi/lo (+ transposed copies) ------
__global__ void k_split()
{
    int m = blockIdx.x;
    const float* P = g_P + m * MSZ;
    for (int e = threadIdx.x; e < MSZ; e += blockDim.x) {
        int i = e >> 7, j = e & 127;
        float x = P[e];
        __nv_bfloat16 hi = __float2bfloat16(x);
        __nv_bfloat16 lo = __float2bfloat16(x - __bfloat162float(hi));
        g_Phi [m * MSZ + e] = hi;
        g_Plo [m * MSZ + e] = lo;
        g_PThi[m * MSZ + j * DIM + i] = hi;   // PT[k][j] = P[j][k]
        g_PTlo[m * MSZ + j * DIM + i] = lo;
    }
}

// ---------------- K3: maps chain via mma.sync bf16 (3-term split) ---------
// D[i,k] = sum_j M[i,j] P[j,k]. A = M row-major (smem), B = PT rows (smem).
// Warp tile 64x32; 8 warps = 2x4 over the 128x128 output.
__global__ void __launch_bounds__(256) k_maps_mma(float* __restrict__ out)
{
    extern __shared__ char smem[];
    uint32_t sb = smem_u32(smem);
    int tid = threadIdx.x, wid = tid >> 5, lane = tid & 31;
    int n = blockIdx.x, h = blockIdx.y;
    int depth = g_depth[n];
    float* outm = out + (size_t)(n * HEADS + h) * MSZ;

    if (depth == 0) {
        for (int e = tid; e < MSZ; e += 256)
            outm[e] = ((e >> 7) == (e & 127)) ? 1.0f : 0.0f;
        return;
    }
    const int* pw = g_pw + n * MAXD;
    if (depth == 1) {
        const float4* src = (const float4*)(g_P + (size_t)(pw[0] * HEADS + h) * MSZ);
        float4* dst = (float4*)outm;
        for (int e = tid; e < MSZ / 4; e += 256) dst[e] = src[e];
        return;
    }

    // prologue: stage M = P(w0) hi/lo and PT(b) hi/lo for b = 0,1
    {
        size_t m0 = (size_t)(pw[0] * HEADS + h) * MSZ;
        size_t mb0 = (size_t)(0 * HEADS + h) * MSZ;
        size_t mb1 = (size_t)(1 * HEADS + h) * MSZ;
        load_pad(sb + OFF_MHI,              g_Phi  + m0,  tid, 256);
        load_pad(sb + OFF_MLO,              g_Plo  + m0,  tid, 256);
        load_pad(sb + OFF_PT + 0 * TILE_B,  g_PThi + mb0, tid, 256);
        load_pad(sb + OFF_PT + 1 * TILE_B,  g_PTlo + mb0, tid, 256);
        load_pad(sb + OFF_PT + 2 * TILE_B,  g_PThi + mb1, tid, 256);
        load_pad(sb + OFF_PT + 3 * TILE_B,  g_PTlo + mb1, tid, 256);
    }
    __syncthreads();

    // per-lane ldmatrix address components
    int m_base = (wid & 1) * 64;
    int n_base = (wid >> 1) * 32;
    int t  = lane >> 3;                    // tile group 0..3
    int r8 = lane & 7;
    int g  = lane >> 2;                    // mma output row-in-8
    int tig = lane & 3;
    // A frag mi: tiles (i0,j0),(i0+8,j0),(i0,j0+8),(i0+8,j0+8)
    uint32_t aOff[4];
#pragma unroll
    for (int mi = 0; mi < 4; mi++) {
        int row = m_base + mi * 16 + (t & 1) * 8 + r8;
        aOff[mi] = (uint32_t)(row * RSB + (t >> 1) * 16);
    }
    // B frag pair p covers ni=2p,2p+1: tiles (n0,j0),(n0,j0+8),(n0+8,j0),(n0+8,j0+8)
    uint32_t bOff[2];
#pragma unroll
    for (int p = 0; p < 2; p++) {
        int row = n_base + p * 16 + (t >> 1) * 8 + r8;
        bOff[p] = (uint32_t)(row * RSB + (t & 1) * 16);
    }

    for (int d = 1; d < depth; d++) {
        int sel = pw[d];
        uint32_t bBase = sb + OFF_PT + (uint32_t)(sel * 2) * TILE_B;  // hi; lo = +TILE_B

        float acc[4][4][4];
#pragma unroll
        for (int mi = 0; mi < 4; mi++)
#pragma unroll
            for (int ni = 0; ni < 4; ni++)
#pragma unroll
                for (int q = 0; q < 4; q++) acc[mi][ni][q] = 0.0f;

#pragma unroll
        for (int kk = 0; kk < 8; kk++) {
            uint32_t kb = (uint32_t)(kk * 32);
            uint32_t Ah[4][4], Al[4][4];
#pragma unroll
            for (int mi = 0; mi < 4; mi++) {
                uint32_t ah = sb + OFF_MHI + aOff[mi] + kb;
                LDSM4(Ah[mi][0], Ah[mi][1], Ah[mi][2], Ah[mi][3], ah);
                LDSM4(Al[mi][0], Al[mi][1], Al[mi][2], Al[mi][3], ah + TILE_B);
            }
            uint32_t Bh[4][2], Bl[4][2];
#pragma unroll
            for (int p = 0; p < 2; p++) {
                uint32_t bh = bBase + bOff[p] + kb;
                uint32_t r0, r1, r2, r3;
                LDSM4(r0, r1, r2, r3, bh);
                Bh[2*p][0] = r0; Bh[2*p][1] = r1; Bh[2*p+1][0] = r2; Bh[2*p+1][1] = r3;
                LDSM4(r0, r1, r2, r3, bh + TILE_B);
                Bl[2*p][0] = r0; Bl[2*p][1] = r1; Bl[2*p+1][0] = r2; Bl[2*p+1][1] = r3;
            }
#pragma unroll
            for (int mi = 0; mi < 4; mi++)
#pragma unroll
                for (int ni = 0; ni < 4; ni++) {
                    MMA16816(acc[mi][ni], Ah[mi], Bh[ni]);
                    MMA16816(acc[mi][ni], Ah[mi], Bl[ni]);
                    MMA16816(acc[mi][ni], Al[mi], Bh[ni]);
                }
        }
        __syncthreads();                   // all reads of M done

        if (d == depth - 1) {
            // final: accumulators -> global f32
#pragma unroll
            for (int mi = 0; mi < 4; mi++) {
                int row0 = m_base + mi * 16 + g;
#pragma unroll
                for (int ni = 0; ni < 4; ni++) {
                    int col = n_base + ni * 8 + tig * 2;
                    *(float2*)(outm + (size_t)row0 * DIM + col) =
                        make_float2(acc[mi][ni][0], acc[mi][ni][1]);
                    *(float2*)(outm + (size_t)(row0 + 8) * DIM + col) =
                        make_float2(acc[mi][ni][2], acc[mi][ni][3]);
                }
            }
        } else {
            // split accumulators -> M hi/lo in smem
#pragma unroll
            for (int mi = 0; mi < 4; mi++) {
                int row0 = m_base + mi * 16 + g;
#pragma unroll
                for (int ni = 0; ni < 4; ni++) {
                    int colb = (n_base + ni * 8 + tig * 2) * 2;
                    float c0 = acc[mi][ni][0], c1 = acc[mi][ni][1];
                    float c2 = acc[mi][ni][2], c3 = acc[mi][ni][3];
                    __nv_bfloat16 h0 = __float2bfloat16(c0);
                    __nv_bfloat16 h1 = __float2bfloat16(c1);
                    __nv_bfloat16 h2 = __float2bfloat16(c2);
                    __nv_bfloat16 h3 = __float2bfloat16(c3);
                    uint32_t hp01 = pack_bf2(c0, c1);   // rounds again; use packed hi
                    uint32_t hp23 = pack_bf2(c2, c3);
                    float l0 = c0 - __bfloat162float(h0);
                    float l1 = c1 - __bfloat162float(h1);
                    float l2 = c2 - __bfloat162float(h2);
                    float l3 = c3 - __bfloat162float(h3);
                    uint32_t lp01 = pack_bf2(l0, l1);
                    uint32_t lp23 = pack_bf2(l2, l3);
                    uint32_t a0 = sb + OFF_MHI + row0 * RSB + colb;
                    uint32_t a1 = sb + OFF_MHI + (row0 + 8) * RSB + colb;
                    asm volatile("st.shared.b32 [%0], %1;" :: "r"(a0), "r"(hp01) : "memory");
                    asm volatile("st.shared.b32 [%0], %1;" :: "r"(a1), "r"(hp23) : "memory");
                    asm volatile("st.shared.b32 [%0], %1;" :: "r"(a0 + TILE_B), "r"(lp01) : "memory");
                    asm volatile("st.shared.b32 [%0], %1;" :: "r"(a1 + TILE_B), "r"(lp23) : "memory");
                }
            }
            __syncthreads();
        }
    }
}

// ---------------- host launcher ----------------
extern "C" void kernel_launch(void* const* d_in, const int* in_sizes, int n_in,
                              void* d_out, int out_size)
{
    const float* prim      = (const float*)d_in[0];
    const int*   positions = (const int*)d_in[1];
    float*       out       = (float*)d_out;
    (void)in_sizes; (void)n_in;

    const int EG_SMEM = (128 * 130 + 128 * 16) * 4;
    cudaFuncSetAttribute(k_maps_mma, cudaFuncAttributeMaxDynamicSharedMemorySize, SMEM_MAPS);
    cudaFuncSetAttribute(k_egemm2, cudaFuncAttributeMaxDynamicSharedMemorySize, EG_SMEM);

    float *pX, *pX2, *pT0, *pT1, *pP;
    cudaGetSymbolAddress((void**)&pX,  g_X);
    cudaGetSymbolAddress((void**)&pX2, g_X2);
    cudaGetSymbolAddress((void**)&pT0, g_T0);
    cudaGetSymbolAddress((void**)&pT1, g_T1);
    cudaGetSymbolAddress((void**)&pP,  g_P);

    const int MAPS_ELEMS  = NTOK * HEADS * MSZ;
    const int STEPS_ELEMS = NTOK * NTOK;
    int write_steps = (out_size >= MAPS_ELEMS + STEPS_ELEMS) ? 1 : 0;
    float* steps_out = out + MAPS_ELEMS;

    k_paths<<<1, 256>>>(positions, steps_out, write_steps);

    // expm: X = skew/2^6; order-8 Taylor (Paterson-Stockmeyer); 6 squarings
    k_skew<<<NMAT, 256>>>(prim);
    const float c2 = 1.0f/2.0f, c3 = 1.0f/6.0f, c4 = 1.0f/24.0f, c5 = 1.0f/120.0f;
    dim3 gg(NMAT, 8);
    k_egemm2<<<gg, 256, EG_SMEM>>>(pX,  pX,  pX2, pX, 0.0f, 0.0f, pT0, 1);
    k_egemm2<<<gg, 256, EG_SMEM>>>(pX2, pT0, pT1, pX, c4, c5, nullptr, 1);
    k_egemm2<<<gg, 256, EG_SMEM>>>(pX2, pT1, pT0, pX, c2, c3, nullptr, 1);
    k_egemm2<<<gg, 256, EG_SMEM>>>(pX2, pT0, pT1, pX, 1.0f, 1.0f, nullptr, 1);
    k_egemm2<<<gg, 256, EG_SMEM>>>(pT1, pT1, pT0, nullptr, 0, 0, nullptr, 0);
    k_egemm2<<<gg, 256, EG_SMEM>>>(pT0, pT0, pT1, nullptr, 0, 0, nullptr, 0);
    k_egemm2<<<gg, 256, EG_SMEM>>>(pT1, pT1, pT0, nullptr, 0, 0, nullptr, 0);
    k_egemm2<<<gg, 256, EG_SMEM>>>(pT0, pT0, pT1, nullptr, 0, 0, nullptr, 0);
    k_egemm2<<<gg, 256, EG_SMEM>>>(pT1, pT1, pT0, nullptr, 0, 0, nullptr, 0);
    k_egemm2<<<gg, 256, EG_SMEM>>>(pT0, pT0, pP,  nullptr, 0, 0, nullptr, 0);

    // split P -> bf16 hi/lo (+transposed)
    k_split<<<NMAT, 256>>>();

    dim3 gm(NTOK, HEADS);
    k_maps_mma<<<gm, 256, SMEM_MAPS>>>(out);
}